// round 3
// baseline (speedup 1.0000x reference)
#include <cuda_runtime.h>
#include <cstdint>

typedef unsigned long long ULL;

// ---------------------------------------------------------------------------
// Problem constants: B=64, N=512, E=1, M=256, F=[1,8,8], K=[3,3], MLP=[512,128]
// ---------------------------------------------------------------------------
#define NODES 512
#define BATCH 64
#define MAXNZ 64   // max nonzeros per row we support (actual ~16)

// ------------------------- device scratch (no allocs) -----------------------
static __device__ int   g_sp_cnt[NODES];
static __device__ short g_sp_cols[NODES * MAXNZ];
static __device__ int   g_s_cnt[NODES];
static __device__ short g_s_cols[NODES * MAXNZ];
static __device__ float g_s_vals[NODES * MAXNZ];

static __device__ float2 g_wc1[24 * NODES * MAXNZ];    // layer1 packed (w, col)
static __device__ float2 g_wc2[192 * NODES * MAXNZ];   // layer2 packed (w, col)

static __device__ float g_x0[NODES * BATCH];           // x transposed [n][b]
static __device__ float g_zs1a[NODES * BATCH];         // S x
static __device__ float g_zs1b[NODES * BATCH];         // S^2 x
static __device__ float g_y1ev[8 * NODES * BATCH];     // layer1 EV output
static __device__ float g_x1[8 * NODES * BATCH];       // layer1 output [g][n][b]
static __device__ float g_zs2a[8 * NODES * BATCH];     // S x1
static __device__ float g_zs2b[8 * NODES * BATCH];     // S^2 x1
static __device__ float g_ypart[64 * NODES * BATCH];   // layer2 EV partials [f][g][n][b]
static __device__ float g_y2[8 * NODES * BATCH];       // layer2 output = yf [i][b]
static __device__ float g_hpart[16 * 512 * BATCH];     // MLP1 splitK partials
static __device__ float g_h1[512 * BATCH];             // MLP1 hidden [j][b]

// ---------------------------------------------------------------------------
// 1) Build sparse structures from S (deterministic, ordered by column index).
//    S structure  : columns where S != 0                     (for LSI part)
//    sp structure : support(|S|+I > ztol) minus [M:,M:]      (for EV part)
// ---------------------------------------------------------------------------
__global__ void k_build(const float* __restrict__ S) {
    int warp = blockIdx.x * (blockDim.x >> 5) + (threadIdx.x >> 5);
    int lane = threadIdx.x & 31;
    if (warp >= NODES) return;
    int m = warp;
    unsigned lt = (1u << lane) - 1u;
    int sc = 0, spc = 0;
    for (int base = 0; base < NODES; base += 32) {
        int n = base + lane;
        float v = S[m * NODES + n];
        bool nz = (v != 0.0f);
        unsigned bs = __ballot_sync(0xffffffffu, nz);
        if (nz) {
            int idx = sc + __popc(bs & lt);
            if (idx < MAXNZ) { g_s_cols[m * MAXNZ + idx] = (short)n; g_s_vals[m * MAXNZ + idx] = v; }
        }
        sc += __popc(bs);
        bool insp = ((fabsf(v) > 1e-9f) || (n == m)) && !((m >= 256) && (n >= 256));
        unsigned bp = __ballot_sync(0xffffffffu, insp);
        if (insp) {
            int idx = spc + __popc(bp & lt);
            if (idx < MAXNZ) g_sp_cols[m * MAXNZ + idx] = (short)n;
        }
        spc += __popc(bp);
    }
    if (lane == 0) {
        g_s_cnt[m]  = sc  < MAXNZ ? sc  : MAXNZ;
        g_sp_cnt[m] = spc < MAXNZ ? spc : MAXNZ;
    }
}

// ---------------------------------------------------------------------------
// 2) Transpose x (B,1,N) -> x0[n][b]
// ---------------------------------------------------------------------------
__global__ void k_transpose(const float* __restrict__ x) {
    int m = blockIdx.x, b = threadIdx.x;
    g_x0[m * BATCH + b] = x[b * NODES + m];
}

// ---------------------------------------------------------------------------
// 3) Pre-gather masked wEV values into packed (w, col) pairs per (plane,row).
//    plane = (f*3+k)*G + g.  Only the ~3% nonzero positions are touched.
// ---------------------------------------------------------------------------
__global__ void k_gather(const float* __restrict__ wEV, int layer) {
    int gw = blockIdx.x * 8 + (threadIdx.x >> 5);
    int lane = threadIdx.x & 31;
    int plane = gw >> 9;
    int m = gw & 511;
    int cnt = g_sp_cnt[m];
    float2* wc = (layer == 1) ? g_wc1 : g_wc2;
    const float* src = wEV + (size_t)plane * (NODES * NODES) + (size_t)m * NODES;
    float2* dst = wc + ((size_t)plane * NODES + m) * MAXNZ;
    for (int j = lane; j < cnt; j += 32) {
        int n = g_sp_cols[m * MAXNZ + j];
        dst[j] = make_float2(__ldg(src + n), __int_as_float(n));
    }
}

// ---------------------------------------------------------------------------
// 4) Sparse S matvec for LSI powers: out[c][m][b] = sum_j Sval * in[c][col][b]
//    step: 0: x0->zs1a | 1: zs1a->zs1b | 2: x1->zs2a | 3: zs2a->zs2b
// ---------------------------------------------------------------------------
__global__ void k_spmv(int step) {
    const float* in; float* out;
    if (step == 0)      { in = g_x0;   out = g_zs1a; }
    else if (step == 1) { in = g_zs1a; out = g_zs1b; }
    else if (step == 2) { in = g_x1;   out = g_zs2a; }
    else                { in = g_zs2a; out = g_zs2b; }
    int c = blockIdx.x >> 9;
    int m = blockIdx.x & 511;
    int b = threadIdx.x;
    int cnt = g_s_cnt[m];
    float acc = 0.f;
#pragma unroll 4
    for (int j = 0; j < cnt; j++)
        acc += g_s_vals[m * MAXNZ + j] * in[((c << 9) + g_s_cols[m * MAXNZ + j]) * BATCH + b];
    out[((c << 9) + m) * BATCH + b] = acc;
}

// ---------------------------------------------------------------------------
// 5) EV chain kernel: one CTA per (f,g,b-half). z resident in shared memory.
//    For k=0..2: z <- Phi_k z ; y += z.  512 threads, 16 warps x 32 rows each.
// ---------------------------------------------------------------------------
__global__ __launch_bounds__(512, 1) void k_evchain(int layer) {
    extern __shared__ float zsm[];                 // [512 rows][32 b] = 64KB
    const int G = (layer == 1) ? 1 : 8;
    const float2* wc = (layer == 1) ? g_wc1 : g_wc2;
    const float*  xin = (layer == 1) ? g_x0 : g_x1;
    float* yout = (layer == 1) ? g_y1ev : g_ypart;

    int h  = blockIdx.x & 1;                       // b-half
    int fg = blockIdx.x >> 1;
    int f  = fg / G, g = fg % G;
    int tid = threadIdx.x, w = tid >> 5, lane = tid & 31;

    // initial z = x slice
    for (int idx = tid; idx < NODES * 32; idx += 512)
        zsm[idx] = xin[((g << 9) + (idx >> 5)) * BATCH + (h << 5) + (idx & 31)];
    __syncthreads();

    float ya[32];
#pragma unroll
    for (int i = 0; i < 32; i++) ya[i] = 0.f;

    for (int k = 0; k < 3; k++) {
        int plane = (f * 3 + k) * G + g;
        float zn[32];
#pragma unroll
        for (int i = 0; i < 32; i++) {
            int m = (i << 4) + w;
            int cnt = g_sp_cnt[m];
            const float2* wr = wc + ((size_t)plane * NODES + m) * MAXNZ;
            float acc = 0.f;
#pragma unroll 4
            for (int j = 0; j < cnt; j++) {
                float2 p = __ldg(wr + j);
                acc += p.x * zsm[(__float_as_int(p.y) << 5) + lane];
            }
            zn[i] = acc;
        }
        __syncthreads();
#pragma unroll
        for (int i = 0; i < 32; i++) {
            int m = (i << 4) + w;
            zsm[(m << 5) + lane] = zn[i];
            ya[i] += zn[i];
        }
        __syncthreads();
    }
#pragma unroll
    for (int i = 0; i < 32; i++) {
        int m = (i << 4) + w;
        yout[((size_t)fg * NODES + m) * BATCH + (h << 5) + lane] = ya[i];
    }
}

// ---------------------------------------------------------------------------
// 6) Combine layer1: x1 = yEV + sum_k wLSI1[f,k] * S^k x + b1[f]
// ---------------------------------------------------------------------------
__global__ void k_combine1(const float* __restrict__ wLSI1, const float* __restrict__ b1) {
    int idx = blockIdx.x * blockDim.x + threadIdx.x;   // 8*512*64
    int f = idx >> 15; int mb = idx & 32767;
    float v = g_y1ev[idx]
        + wLSI1[f * 3 + 0] * g_x0[mb]
        + wLSI1[f * 3 + 1] * g_zs1a[mb]
        + wLSI1[f * 3 + 2] * g_zs1b[mb]
        + b1[f];
    g_x1[idx] = v;
}

// ---------------------------------------------------------------------------
// 7) Combine layer2: y2 = sum_g ypart + sum_{k,g} wLSI2[f,k,g] * S^k x1 + b2[f]
// ---------------------------------------------------------------------------
__global__ void k_combine2(const float* __restrict__ wLSI2, const float* __restrict__ b2) {
    int idx = blockIdx.x * blockDim.x + threadIdx.x;   // 8*512*64
    int f = idx >> 15; int mb = idx & 32767;
    float acc = b2[f];
#pragma unroll
    for (int g = 0; g < 8; g++) {
        acc += g_ypart[(((f << 3) + g) << 15) + mb];
        acc += wLSI2[f * 24 + g]      * g_x1[(g << 15) + mb];
        acc += wLSI2[f * 24 + 8 + g]  * g_zs2a[(g << 15) + mb];
        acc += wLSI2[f * 24 + 16 + g] * g_zs2b[(g << 15) + mb];
    }
    g_y2[idx] = acc;
}

// ---------------------------------------------------------------------------
// 8) MLP layer 1: h[j][b] = sum_i W1[j][i] * yf[i][b]  (splitK, f32x2 packed)
// ---------------------------------------------------------------------------
__device__ __forceinline__ ULL ffma2(ULL a, ULL b, ULL c) {
    ULL d; asm("fma.rn.f32x2 %0, %1, %2, %3;" : "=l"(d) : "l"(a), "l"(b), "l"(c));
    return d;
}
__device__ __forceinline__ ULL packdup(float x) {
    ULL r; asm("mov.b64 %0, {%1, %1};" : "=l"(r) : "f"(x));
    return r;
}

__global__ __launch_bounds__(256) void k_mlp1(const float* __restrict__ W1) {
    __shared__ ULL sW[64 * 32];                      // [j][ii] as (w,w) packed, 16KB
    __shared__ __align__(16) float sX[32 * 64];      // [ii][b], 8KB
    int jt = blockIdx.x;      // 0..7 : 64 output j each
    int kt = blockIdx.y;      // 0..15: 256 i each
    int tid = threadIdx.x;
    int bp = tid & 31;        // b-pair: handles b = 2bp, 2bp+1
    int jg = tid >> 5;        // 0..7 : 8 j each
    ULL acc[8];
#pragma unroll
    for (int jj = 0; jj < 8; jj++) acc[jj] = 0ull;

    for (int ic = 0; ic < 8; ic++) {
        int i0 = kt * 256 + ic * 32;
        {
            int ii = tid & 31; int jr0 = tid >> 5;
#pragma unroll
            for (int q = 0; q < 8; q++) {
                int jr = jr0 + (q << 3);
                float wv = W1[(size_t)(jt * 64 + jr) * 4096 + i0 + ii];
                sW[(jr << 5) + ii] = packdup(wv);
            }
            int b = tid & 63; int ii0 = tid >> 6;
#pragma unroll
            for (int q = 0; q < 8; q++) {
                int ii2 = ii0 + (q << 2);
                sX[(ii2 << 6) + b] = g_y2[(size_t)(i0 + ii2) * BATCH + b];
            }
        }
        __syncthreads();
#pragma unroll
        for (int ii = 0; ii < 32; ii++) {
            ULL xv = *reinterpret_cast<const ULL*>(&sX[(ii << 6) + (bp << 1)]);
#pragma unroll
            for (int jj = 0; jj < 8; jj++)
                acc[jj] = ffma2(sW[(((jg << 3) + jj) << 5) + ii], xv, acc[jj]);
        }
        __syncthreads();
    }
#pragma unroll
    for (int jj = 0; jj < 8; jj++) {
        int j = jt * 64 + (jg << 3) + jj;
        *reinterpret_cast<ULL*>(&g_hpart[((kt << 9) + j) * BATCH + (bp << 1)]) = acc[jj];
    }
}

__global__ void k_hreduce(const float* __restrict__ bW1) {
    int idx = blockIdx.x * blockDim.x + threadIdx.x;   // 512*64
    float s = bW1[idx >> 6];
#pragma unroll
    for (int kt = 0; kt < 16; kt++) s += g_hpart[(kt << 15) + idx];
    g_h1[idx] = s;
}

// ---------------------------------------------------------------------------
// 9) MLP layer 2: out[b][j2] = sum_j W2[j2][j] * h[j][b] + bW2[j2]
// ---------------------------------------------------------------------------
__global__ void k_mlp2(const float* __restrict__ W2, const float* __restrict__ bW2,
                       float* __restrict__ out) {
    int j2 = blockIdx.x; int b = threadIdx.x;
    float acc = 0.f;
#pragma unroll 8
    for (int j = 0; j < 512; j++)
        acc += W2[j2 * 512 + j] * g_h1[(j << 6) + b];
    out[b * 128 + j2] = acc + bW2[j2];
}

// ---------------------------------------------------------------------------
// launch
// ---------------------------------------------------------------------------
extern "C" void kernel_launch(void* const* d_in, const int* in_sizes, int n_in,
                              void* d_out, int out_size) {
    const float* x     = (const float*)d_in[0];
    const float* S     = (const float*)d_in[1];
    const float* wEV1  = (const float*)d_in[2];
    const float* wLSI1 = (const float*)d_in[3];
    const float* b1    = (const float*)d_in[4];
    const float* wEV2  = (const float*)d_in[5];
    const float* wLSI2 = (const float*)d_in[6];
    const float* b2    = (const float*)d_in[7];
    const float* W1    = (const float*)d_in[8];
    const float* bW1   = (const float*)d_in[9];
    const float* W2    = (const float*)d_in[10];
    const float* bW2   = (const float*)d_in[11];
    float* out = (float*)d_out;

    cudaFuncSetAttribute(k_evchain, cudaFuncAttributeMaxDynamicSharedMemorySize, 65536);

    k_build<<<32, 512>>>(S);
    k_transpose<<<512, 64>>>(x);
    k_gather<<<12288, 256>>>(wEV2, 2);   // big gather first (DRAM-bound)
    k_gather<<<1536, 256>>>(wEV1, 1);
    k_spmv<<<512, 64>>>(0);              // S x
    k_spmv<<<512, 64>>>(1);              // S^2 x
    k_evchain<<<16, 512, 65536>>>(1);    // layer1 EV chains
    k_combine1<<<1024, 256>>>(wLSI1, b1);
    k_spmv<<<4096, 64>>>(2);             // S x1
    k_spmv<<<4096, 64>>>(3);             // S^2 x1
    k_evchain<<<128, 512, 65536>>>(2);   // layer2 EV chains
    k_combine2<<<1024, 256>>>(wLSI2, b2);
    dim3 gm1(8, 16);
    k_mlp1<<<gm1, 256>>>(W1);
    k_hreduce<<<512, 64>>>(bW1);
    k_mlp2<<<128, 64>>>(W2, bW2, out);
}

// round 5
// speedup vs baseline: 1.1036x; 1.1036x over previous
#include <cuda_runtime.h>
#include <cstdint>

typedef unsigned long long ULL;

// ---------------------------------------------------------------------------
// Problem constants: B=64, N=512, E=1, M=256, F=[1,8,8], K=[3,3], MLP=[512,128]
// ---------------------------------------------------------------------------
#define NODES 512
#define BATCH 64
#define MAXNZ 64   // max nonzeros per row supported (actual ~16, max ~35)

// ------------------------- device scratch (no allocs) -----------------------
static __device__ int   g_sp_cnt[NODES];
static __device__ short g_sp_cols[NODES * MAXNZ];
static __device__ int   g_s_cnt[NODES];
static __device__ short g_s_cols[NODES * MAXNZ];
static __device__ float g_s_vals[NODES * MAXNZ];

static __device__ float g_w1[24 * NODES * MAXNZ];      // layer1 packed weights
static __device__ float g_w2[192 * NODES * MAXNZ];     // layer2 packed weights

static __device__ float g_x0[NODES * BATCH];           // x transposed [n][b]
static __device__ float g_zs1a[NODES * BATCH];         // S x
static __device__ float g_zs1b[NODES * BATCH];         // S^2 x
static __device__ float g_x1[8 * NODES * BATCH];       // layer1 output [g][n][b]
static __device__ float g_zs2a[8 * NODES * BATCH];     // S x1
static __device__ float g_zs2b[8 * NODES * BATCH];     // S^2 x1
static __device__ float g_ypart[64 * NODES * BATCH];   // layer2 EV partials [f][g][n][b]
static __device__ float g_y2[8 * NODES * BATCH];       // layer2 output = yf [i][b]
static __device__ float g_hpart[16 * 512 * BATCH];     // MLP1 splitK partials
static __device__ float g_h1[512 * BATCH];             // MLP1 hidden [j][b]

// ---------------------------------------------------------------------------
// 1) Build sparse structures from S. Prefetch whole row into 16 regs (MLP=16)
//    before the ballot/compaction rounds.
// ---------------------------------------------------------------------------
__global__ void k_build(const float* __restrict__ S) {
    int warp = blockIdx.x * (blockDim.x >> 5) + (threadIdx.x >> 5);
    int lane = threadIdx.x & 31;
    if (warp >= NODES) return;
    int m = warp;
    unsigned lt = (1u << lane) - 1u;
    float v[16];
#pragma unroll
    for (int r = 0; r < 16; r++) v[r] = __ldg(S + (m << 9) + (r << 5) + lane);
    int sc = 0, spc = 0;
#pragma unroll
    for (int r = 0; r < 16; r++) {
        int n = (r << 5) + lane;
        bool nz = (v[r] != 0.0f);
        unsigned bs = __ballot_sync(0xffffffffu, nz);
        if (nz) {
            int idx = sc + __popc(bs & lt);
            if (idx < MAXNZ) { g_s_cols[m * MAXNZ + idx] = (short)n; g_s_vals[m * MAXNZ + idx] = v[r]; }
        }
        sc += __popc(bs);
        bool insp = ((fabsf(v[r]) > 1e-9f) || (n == m)) && !((m >= 256) && (n >= 256));
        unsigned bp = __ballot_sync(0xffffffffu, insp);
        if (insp) {
            int idx = spc + __popc(bp & lt);
            if (idx < MAXNZ) g_sp_cols[m * MAXNZ + idx] = (short)n;
        }
        spc += __popc(bp);
    }
    if (lane == 0) {
        g_s_cnt[m]  = sc  < MAXNZ ? sc  : MAXNZ;
        g_sp_cnt[m] = spc < MAXNZ ? spc : MAXNZ;
    }
}

// ---------------------------------------------------------------------------
// 2) Transpose x (B,1,N) -> x0[n][b]
// ---------------------------------------------------------------------------
__global__ void k_transpose(const float* __restrict__ x) {
    int m = blockIdx.x, b = threadIdx.x;
    g_x0[m * BATCH + b] = x[b * NODES + m];
}

// ---------------------------------------------------------------------------
// 3) Pre-gather masked wEV into packed weights. One warp handles ONE row for
//    EIGHT planes (shared sparsity pattern): col list loaded once, then 8
//    independent scattered LDGs (MLP=8/thread). Weight-only output.
// ---------------------------------------------------------------------------
__global__ __launch_bounds__(256) void k_gather(const float* __restrict__ wEV,
                                                float* __restrict__ wout) {
    int gw = blockIdx.x * 8 + (threadIdx.x >> 5);
    int lane = threadIdx.x & 31;
    int pg = gw >> 9;            // plane-group of 8
    int m = gw & 511;
    int cnt = g_sp_cnt[m];
    for (int jb = 0; jb < cnt; jb += 32) {
        bool act = (jb + lane) < cnt;
        int col = act ? (int)g_sp_cols[(m << 6) + jb + lane] : 0;
        const float* src = wEV + ((size_t)(pg * 8) << 18) + (m << 9) + col;
        float v[8];
#pragma unroll
        for (int q = 0; q < 8; q++) v[q] = act ? __ldg(src + ((size_t)q << 18)) : 0.f;
#pragma unroll
        for (int q = 0; q < 8; q++)
            if (act) wout[(((size_t)(pg * 8 + q) << 9) + m) * MAXNZ + jb + lane] = v[q];
    }
}

// ---------------------------------------------------------------------------
// 4) Sparse S matvec (LSI powers), shuffle-broadcast form. One warp handles
//    (c, m, b-half): lanes cooperatively load (val,col), broadcast via shfl,
//    per-j coalesced LDG of the input rows (independent loads).
// ---------------------------------------------------------------------------
__global__ __launch_bounds__(256) void k_spmv(int step, int nc) {
    const float* in; float* out;
    if (step == 0)      { in = g_x0;   out = g_zs1a; }
    else if (step == 1) { in = g_zs1a; out = g_zs1b; }
    else if (step == 2) { in = g_x1;   out = g_zs2a; }
    else                { in = g_zs2a; out = g_zs2b; }
    int gw = blockIdx.x * 8 + (threadIdx.x >> 5);
    int lane = threadIdx.x & 31;
    int c = gw >> 10;
    if (c >= nc) return;
    int m = (gw >> 1) & 511;
    int h = gw & 1;
    int cnt = g_s_cnt[m];
    float acc = 0.f;
    for (int jb = 0; jb < cnt; jb += 32) {
        int jn = cnt - jb; if (jn > 32) jn = 32;
        float sv = 0.f; int cv = 0;
        if (lane < jn) {
            cv = (int)g_s_cols[(m << 6) + jb + lane];
            sv = g_s_vals[(m << 6) + jb + lane];
        }
#pragma unroll 8
        for (int j = 0; j < jn; j++) {
            float wj = __shfl_sync(0xffffffffu, sv, j);
            int cj   = __shfl_sync(0xffffffffu, cv, j);
            acc += wj * __ldg(in + ((c << 9) + cj) * BATCH + (h << 5) + lane);
        }
    }
    out[((c << 9) + m) * BATCH + (h << 5) + lane] = acc;
}

// ---------------------------------------------------------------------------
// 5) EV chain kernel: one CTA per (f,g,b-half). z ping-pong in shared memory
//    (2 x 64KB), ONE sync per k-step. Weight rows loaded coalesced and
//    broadcast via shfl. Layer1 fuses the LSI combine into the epilogue.
// ---------------------------------------------------------------------------
__global__ __launch_bounds__(512, 1) void k_evchain(int layer,
                                                    const float* __restrict__ wLSI1,
                                                    const float* __restrict__ b1) {
    extern __shared__ float zsm[];                 // 2 x [512][32]
    __shared__ int scnt[NODES];
    const int G = (layer == 1) ? 1 : 8;
    const float* wbase = (layer == 1) ? g_w1 : g_w2;
    const float* xin   = (layer == 1) ? g_x0 : g_x1;

    int h  = blockIdx.x & 1;
    int fg = blockIdx.x >> 1;
    int f  = fg >> ((layer == 1) ? 0 : 3);
    int g  = (layer == 1) ? 0 : (fg & 7);
    int tid = threadIdx.x, w = tid >> 5, lane = tid & 31;

    scnt[tid] = g_sp_cnt[tid];
    float* zr = zsm;
    float* zw = zsm + NODES * 32;
    // initial z = x slice
    for (int idx = tid; idx < NODES * 32; idx += 512)
        zr[idx] = xin[((g << 9) + (idx >> 5)) * BATCH + (h << 5) + (idx & 31)];
    __syncthreads();

    float ya[32];
#pragma unroll
    for (int i = 0; i < 32; i++) ya[i] = 0.f;

    for (int k = 0; k < 3; k++) {
        int plane = (f * 3 + k) * G + g;
        const float* wpl = wbase + ((size_t)plane << 9) * MAXNZ;
#pragma unroll 4
        for (int i = 0; i < 32; i++) {
            int m = (i << 4) + w;
            int cnt = scnt[m];
            const float* wr = wpl + (m << 6);
            float acc = 0.f;
            for (int jb = 0; jb < cnt; jb += 32) {
                int jn = cnt - jb; if (jn > 32) jn = 32;
                float wv = 0.f; int cv = 0;
                if (lane < jn) {
                    cv = (int)g_sp_cols[(m << 6) + jb + lane];
                    wv = wr[jb + lane];
                }
#pragma unroll 8
                for (int j = 0; j < jn; j++) {
                    float wj = __shfl_sync(0xffffffffu, wv, j);
                    int cj   = __shfl_sync(0xffffffffu, cv, j);
                    acc += wj * zr[(cj << 5) + lane];
                }
            }
            zw[(m << 5) + lane] = acc;
            ya[i] += acc;
        }
        __syncthreads();
        float* t = zr; zr = zw; zw = t;
    }

    if (layer == 1) {
        // fused combine1: x1 = yEV + sum_k wLSI1[f,k] S^k x + b1[f]
        float wl0 = wLSI1[f * 3 + 0], wl1 = wLSI1[f * 3 + 1], wl2 = wLSI1[f * 3 + 2];
        float bb = b1[f];
#pragma unroll
        for (int i = 0; i < 32; i++) {
            int m = (i << 4) + w;
            int off = (m << 6) + (h << 5) + lane;
            float v = ya[i] + wl0 * g_x0[off] + wl1 * g_zs1a[off] + wl2 * g_zs1b[off] + bb;
            g_x1[(f << 15) + off] = v;
        }
    } else {
#pragma unroll
        for (int i = 0; i < 32; i++) {
            int m = (i << 4) + w;
            g_ypart[((size_t)fg << 15) + (m << 6) + (h << 5) + lane] = ya[i];
        }
    }
}

// ---------------------------------------------------------------------------
// 6) Combine layer2: y2 = sum_g ypart + sum_{k,g} wLSI2[f,k,g] * S^k x1 + b2[f]
// ---------------------------------------------------------------------------
__global__ void k_combine2(const float* __restrict__ wLSI2, const float* __restrict__ b2) {
    int idx = blockIdx.x * blockDim.x + threadIdx.x;   // 8*512*64
    int f = idx >> 15; int mb = idx & 32767;
    float acc = b2[f];
#pragma unroll
    for (int g = 0; g < 8; g++) {
        acc += g_ypart[(((f << 3) + g) << 15) + mb];
        acc += wLSI2[f * 24 + g]      * g_x1[(g << 15) + mb];
        acc += wLSI2[f * 24 + 8 + g]  * g_zs2a[(g << 15) + mb];
        acc += wLSI2[f * 24 + 16 + g] * g_zs2b[(g << 15) + mb];
    }
    g_y2[idx] = acc;
}

// ---------------------------------------------------------------------------
// 7) MLP layer 1: h[j][b] = sum_i W1[j][i] * yf[i][b]  (splitK, f32x2 packed)
// ---------------------------------------------------------------------------
__device__ __forceinline__ ULL ffma2(ULL a, ULL b, ULL c) {
    ULL d; asm("fma.rn.f32x2 %0, %1, %2, %3;" : "=l"(d) : "l"(a), "l"(b), "l"(c));
    return d;
}
__device__ __forceinline__ ULL packdup(float x) {
    ULL r; asm("mov.b64 %0, {%1, %1};" : "=l"(r) : "f"(x));
    return r;
}

__global__ __launch_bounds__(256) void k_mlp1(const float* __restrict__ W1) {
    __shared__ ULL sW[64 * 32];                      // [j][ii] packed (w,w)
    __shared__ __align__(16) float sX[32 * 64];      // [ii][b]
    int jt = blockIdx.x;      // 0..7 : 64 output j each
    int kt = blockIdx.y;      // 0..15: 256 i each
    int tid = threadIdx.x;
    int bp = tid & 31;        // b-pair
    int jg = tid >> 5;        // 8 j each
    ULL acc[8];
#pragma unroll
    for (int jj = 0; jj < 8; jj++) acc[jj] = 0ull;

    for (int ic = 0; ic < 8; ic++) {
        int i0 = kt * 256 + ic * 32;
        {
            int ii = tid & 31; int jr0 = tid >> 5;
#pragma unroll
            for (int q = 0; q < 8; q++) {
                int jr = jr0 + (q << 3);
                float wv = W1[(size_t)(jt * 64 + jr) * 4096 + i0 + ii];
                sW[(jr << 5) + ii] = packdup(wv);
            }
            int b = tid & 63; int ii0 = tid >> 6;
#pragma unroll
            for (int q = 0; q < 8; q++) {
                int ii2 = ii0 + (q << 2);
                sX[(ii2 << 6) + b] = g_y2[(size_t)(i0 + ii2) * BATCH + b];
            }
        }
        __syncthreads();
#pragma unroll
        for (int ii = 0; ii < 32; ii++) {
            ULL xv = *reinterpret_cast<const ULL*>(&sX[(ii << 6) + (bp << 1)]);
#pragma unroll
            for (int jj = 0; jj < 8; jj++)
                acc[jj] = ffma2(sW[(((jg << 3) + jj) << 5) + ii], xv, acc[jj]);
        }
        __syncthreads();
    }
#pragma unroll
    for (int jj = 0; jj < 8; jj++) {
        int j = jt * 64 + (jg << 3) + jj;
        *reinterpret_cast<ULL*>(&g_hpart[((kt << 9) + j) * BATCH + (bp << 1)]) = acc[jj];
    }
}

__global__ void k_hreduce(const float* __restrict__ bW1) {
    int idx = blockIdx.x * blockDim.x + threadIdx.x;   // 512*64
    float s = bW1[idx >> 6];
#pragma unroll
    for (int kt = 0; kt < 16; kt++) s += g_hpart[(kt << 15) + idx];
    g_h1[idx] = s;
}

// ---------------------------------------------------------------------------
// 8) MLP layer 2: out[b][j2] = sum_j W2[j2][j] * h[j][b] + bW2[j2]
// ---------------------------------------------------------------------------
__global__ void k_mlp2(const float* __restrict__ W2, const float* __restrict__ bW2,
                       float* __restrict__ out) {
    int j2 = blockIdx.x; int b = threadIdx.x;
    float acc = 0.f;
#pragma unroll 8
    for (int j = 0; j < 512; j++)
        acc += W2[j2 * 512 + j] * g_h1[(j << 6) + b];
    out[b * 128 + j2] = acc + bW2[j2];
}

// ---------------------------------------------------------------------------
// launch
// ---------------------------------------------------------------------------
extern "C" void kernel_launch(void* const* d_in, const int* in_sizes, int n_in,
                              void* d_out, int out_size) {
    const float* x     = (const float*)d_in[0];
    const float* S     = (const float*)d_in[1];
    const float* wEV1  = (const float*)d_in[2];
    const float* wLSI1 = (const float*)d_in[3];
    const float* b1    = (const float*)d_in[4];
    const float* wEV2  = (const float*)d_in[5];
    const float* wLSI2 = (const float*)d_in[6];
    const float* b2    = (const float*)d_in[7];
    const float* W1    = (const float*)d_in[8];
    const float* bW1   = (const float*)d_in[9];
    const float* W2    = (const float*)d_in[10];
    const float* bW2   = (const float*)d_in[11];
    float* out = (float*)d_out;

    float* w1p; cudaGetSymbolAddress((void**)&w1p, g_w1);
    float* w2p; cudaGetSymbolAddress((void**)&w2p, g_w2);
    cudaFuncSetAttribute(k_evchain, cudaFuncAttributeMaxDynamicSharedMemorySize, 131072);

    k_build<<<32, 512>>>(S);
    k_transpose<<<512, 64>>>(x);
    k_gather<<<1536, 256>>>(wEV2, w2p);       // 24 plane-groups x 512 rows
    k_gather<<<192, 256>>>(wEV1, w1p);        // 3 plane-groups x 512 rows
    k_spmv<<<128, 256>>>(0, 1);               // S x
    k_spmv<<<128, 256>>>(1, 1);               // S^2 x
    k_evchain<<<16, 512, 131072>>>(1, wLSI1, b1);   // layer1 EV + fused combine1
    k_spmv<<<1024, 256>>>(2, 8);              // S x1
    k_spmv<<<1024, 256>>>(3, 8);              // S^2 x1
    k_evchain<<<128, 512, 131072>>>(2, wLSI1, b1);  // layer2 EV chains
    k_combine2<<<1024, 256>>>(wLSI2, b2);
    dim3 gm1(8, 16);
    k_mlp1<<<gm1, 256>>>(W1);
    k_hreduce<<<512, 64>>>(bW1);
    k_mlp2<<<128, 64>>>(W2, bW2, out);
}

// round 7
// speedup vs baseline: 1.3616x; 1.2338x over previous
#include <cuda_runtime.h>
#include <cstdint>

typedef unsigned long long ULL;

// ---------------------------------------------------------------------------
// Problem constants: B=64, N=512, E=1, M=256, F=[1,8,8], K=[3,3], MLP=[512,128]
// ---------------------------------------------------------------------------
#define NODES 512
#define BATCH 64
#define MAXNZ 64   // max nonzeros per row supported (actual ~16, max ~35)

// ------------------------- device scratch (no allocs) -----------------------
static __device__ int   g_sp_cnt[NODES];
static __device__ short g_sp_cols[NODES * MAXNZ];
static __device__ int   g_s_cnt[NODES];
static __device__ short g_s_cols[NODES * MAXNZ];
static __device__ float g_s_vals[NODES * MAXNZ];

static __device__ float g_x0[NODES * BATCH];           // x transposed [n][b]
static __device__ float g_zs1a[NODES * BATCH];         // S x
static __device__ float g_zs1b[NODES * BATCH];         // S^2 x
static __device__ float g_x1[8 * NODES * BATCH];       // layer1 output [g][n][b]
static __device__ float g_zs2a[8 * NODES * BATCH];     // S x1
static __device__ float g_zs2b[8 * NODES * BATCH];     // S^2 x1
static __device__ float g_ypart[64 * NODES * BATCH];   // layer2 EV partials [fg][n][b]
static __device__ float g_y2[8 * NODES * BATCH];       // layer2 output = yf [i][b]
static __device__ float g_hpart[16 * 512 * BATCH];     // MLP1 splitK partials
static __device__ float g_h1[512 * BATCH];             // MLP1 hidden [j][b]

// ---------------------------------------------------------------------------
// 1) Build sparse structures from S + transpose x, in one kernel.
//    Blocks 0..31: build (16 warps = 16 rows each). Blocks 32..63: transpose.
// ---------------------------------------------------------------------------
__global__ __launch_bounds__(512) void k_build(const float* __restrict__ S,
                                               const float* __restrict__ x) {
    if (blockIdx.x >= 32) {
        // transpose x (B,1,N) -> x0[n][b] via 32x32 smem tiles
        __shared__ float tile[32][33];
        int tt = blockIdx.x - 32;        // 0..31
        int mt = tt >> 1, bt = tt & 1;   // 16 m-tiles x 2 b-tiles
        int tx = threadIdx.x & 31, ty0 = threadIdx.x >> 5;  // 16 rows, 2 passes
#pragma unroll
        for (int p = 0; p < 2; p++) {
            int ty = ty0 + (p << 4);
            tile[ty][tx] = x[(bt * 32 + ty) * NODES + mt * 32 + tx];
        }
        __syncthreads();
#pragma unroll
        for (int p = 0; p < 2; p++) {
            int ty = ty0 + (p << 4);
            g_x0[(mt * 32 + ty) * BATCH + bt * 32 + tx] = tile[tx][ty];
        }
        return;
    }
    int m = blockIdx.x * 16 + (threadIdx.x >> 5);
    int lane = threadIdx.x & 31;
    unsigned lt = (1u << lane) - 1u;
    float v[16];
#pragma unroll
    for (int r = 0; r < 16; r++) v[r] = __ldg(S + (m << 9) + (r << 5) + lane);
    int sc = 0, spc = 0;
#pragma unroll
    for (int r = 0; r < 16; r++) {
        int n = (r << 5) + lane;
        bool nz = (v[r] != 0.0f);
        unsigned bs = __ballot_sync(0xffffffffu, nz);
        if (nz) {
            int idx = sc + __popc(bs & lt);
            if (idx < MAXNZ) { g_s_cols[m * MAXNZ + idx] = (short)n; g_s_vals[m * MAXNZ + idx] = v[r]; }
        }
        sc += __popc(bs);
        bool insp = ((fabsf(v[r]) > 1e-9f) || (n == m)) && !((m >= 256) && (n >= 256));
        unsigned bp = __ballot_sync(0xffffffffu, insp);
        if (insp) {
            int idx = spc + __popc(bp & lt);
            if (idx < MAXNZ) g_sp_cols[m * MAXNZ + idx] = (short)n;
        }
        spc += __popc(bp);
    }
    if (lane == 0) {
        g_s_cnt[m]  = sc  < MAXNZ ? sc  : MAXNZ;
        g_sp_cnt[m] = spc < MAXNZ ? spc : MAXNZ;
    }
}

// ---------------------------------------------------------------------------
// 2) Sparse S matvec (LSI powers), shuffle-broadcast form.
// ---------------------------------------------------------------------------
__global__ __launch_bounds__(256) void k_spmv(int step, int nc) {
    const float* in; float* out;
    if (step == 0)      { in = g_x0;   out = g_zs1a; }
    else if (step == 1) { in = g_zs1a; out = g_zs1b; }
    else if (step == 2) { in = g_x1;   out = g_zs2a; }
    else                { in = g_zs2a; out = g_zs2b; }
    int gw = blockIdx.x * 8 + (threadIdx.x >> 5);
    int lane = threadIdx.x & 31;
    int c = gw >> 10;
    if (c >= nc) return;
    int m = (gw >> 1) & 511;
    int h = gw & 1;
    int cnt = g_s_cnt[m];
    float acc = 0.f;
    for (int jb = 0; jb < cnt; jb += 32) {
        int jn = cnt - jb; if (jn > 32) jn = 32;
        float sv = 0.f; int cv = 0;
        if (lane < jn) {
            cv = (int)g_s_cols[(m << 6) + jb + lane];
            sv = g_s_vals[(m << 6) + jb + lane];
        }
#pragma unroll 8
        for (int j = 0; j < jn; j++) {
            float wj = __shfl_sync(0xffffffffu, sv, j);
            int cj   = __shfl_sync(0xffffffffu, cv, j);
            acc += wj * __ldg(in + ((c << 9) + cj) * BATCH + (h << 5) + lane);
        }
    }
    out[((c << 9) + m) * BATCH + (h << 5) + lane] = acc;
}

// ---------------------------------------------------------------------------
// 3) EV chain kernel, reading wEV DIRECTLY (each weight used exactly once, so
//    packing was pure overhead). One CTA per (f,g,b-half). z ping-pong in
//    dynamic smem; cols cached in static smem; depth-2 row prefetch pipeline
//    that legally crosses the per-k __syncthreads (regs only).
// ---------------------------------------------------------------------------
__device__ __forceinline__ void pfrow(const float* __restrict__ wEV, size_t pl,
                                      int m, int lane, const int* scnt,
                                      const short* scols,
                                      int& cnt, int& cv, float& wv) {
    cnt = scnt[m];
    int c = cnt < 32 ? cnt : 32;
    cv = 0; wv = 0.f;
    if (lane < c) {
        cv = scols[(m << 5) + lane];
        wv = __ldg(wEV + (pl << 18) + (m << 9) + cv);
    }
}

__global__ __launch_bounds__(512, 1) void k_evchain(int layer,
                                                    const float* __restrict__ wEV,
                                                    const float* __restrict__ wLSI1,
                                                    const float* __restrict__ b1) {
    extern __shared__ float zsm[];                 // 2 x [512][32] = 128KB
    __shared__ int   scnt[NODES];
    __shared__ short scols[NODES * 32];            // first 32 cols per row
    const int G = (layer == 1) ? 1 : 8;
    const float* xin = (layer == 1) ? g_x0 : g_x1;

    int h  = blockIdx.x & 1;
    int fg = blockIdx.x >> 1;
    int f  = (layer == 1) ? fg : (fg >> 3);
    int g  = (layer == 1) ? 0 : (fg & 7);
    int tid = threadIdx.x, w = tid >> 5, lane = tid & 31;

    scnt[tid] = g_sp_cnt[tid];
    for (int idx = tid; idx < NODES * 32; idx += 512)
        scols[idx] = g_sp_cols[((idx >> 5) << 6) + (idx & 31)];

    float* zr = zsm;
    float* zw = zsm + NODES * 32;
    for (int idx = tid; idx < NODES * 32; idx += 512)
        zr[idx] = xin[((g << 9) + (idx >> 5)) * BATCH + (h << 5) + (idx & 31)];
    __syncthreads();

    const int pbase = f * 3 * G + g;  // plane(t) = pbase + (t>>5)*G

    float ya[32];
#pragma unroll
    for (int i = 0; i < 32; i++) ya[i] = 0.f;

    // pipeline prologue: prefetch t=0, t=1
    int cnt0, cv0, cnt1, cv1; float wv0, wv1;
    pfrow(wEV, (size_t)pbase, w, lane, scnt, scols, cnt0, cv0, wv0);
    pfrow(wEV, (size_t)pbase, w + 16, lane, scnt, scols, cnt1, cv1, wv1);

    for (int t = 0; t < 96; t++) {
        // prefetch t+2 first (overlaps with compute below)
        int cnt2 = 0, cv2 = 0; float wv2 = 0.f;
        int t2 = t + 2;
        if (t2 < 96) {
            size_t pl2 = (size_t)(pbase + (t2 >> 5) * G);
            pfrow(wEV, pl2, ((t2 & 31) << 4) + w, lane, scnt, scols, cnt2, cv2, wv2);
        }
        int m = ((t & 31) << 4) + w;
        float acc = 0.f;
        int jn = cnt0 < 32 ? cnt0 : 32;
#pragma unroll 4
        for (int j = 0; j < jn; j++) {
            float wj = __shfl_sync(0xffffffffu, wv0, j);
            int   cj = __shfl_sync(0xffffffffu, cv0, j);
            acc += wj * zr[(cj << 5) + lane];
        }
        if (cnt0 > 32) {                               // rare tail
            size_t pl = (size_t)(pbase + (t >> 5) * G);
            int rem = cnt0 - 32;
            int cvt = 0; float wvt = 0.f;
            if (lane < rem) {
                cvt = (int)g_sp_cols[(m << 6) + 32 + lane];
                wvt = __ldg(wEV + (pl << 18) + (m << 9) + cvt);
            }
            for (int j = 0; j < rem; j++) {
                float wj = __shfl_sync(0xffffffffu, wvt, j);
                int   cj = __shfl_sync(0xffffffffu, cvt, j);
                acc += wj * zr[(cj << 5) + lane];
            }
        }
        zw[(m << 5) + lane] = acc;
        ya[t & 31] += acc;
        if ((t & 31) == 31) {
            __syncthreads();
            float* tmp = zr; zr = zw; zw = tmp;
        }
        cnt0 = cnt1; cv0 = cv1; wv0 = wv1;
        cnt1 = cnt2; cv1 = cv2; wv1 = wv2;
    }

    if (layer == 1) {
        // fused combine1: x1 = yEV + sum_k wLSI1[f,k] S^k x + b1[f]
        float wl0 = wLSI1[f * 3 + 0], wl1 = wLSI1[f * 3 + 1], wl2 = wLSI1[f * 3 + 2];
        float bb = b1[f];
#pragma unroll
        for (int i = 0; i < 32; i++) {
            int m = (i << 4) + w;
            int off = (m << 6) + (h << 5) + lane;
            g_x1[(f << 15) + off] = ya[i] + wl0 * g_x0[off] + wl1 * g_zs1a[off]
                                  + wl2 * g_zs1b[off] + bb;
        }
    } else {
#pragma unroll
        for (int i = 0; i < 32; i++) {
            int m = (i << 4) + w;
            g_ypart[((size_t)fg << 15) + (m << 6) + (h << 5) + lane] = ya[i];
        }
    }
}

// ---------------------------------------------------------------------------
// 4) Combine layer2: y2 = sum_g ypart + sum_{k,g} wLSI2[f,k,g] * S^k x1 + b2[f]
// ---------------------------------------------------------------------------
__global__ void k_combine2(const float* __restrict__ wLSI2, const float* __restrict__ b2) {
    int idx = blockIdx.x * blockDim.x + threadIdx.x;   // 8*512*64
    int f = idx >> 15; int mb = idx & 32767;
    float acc = b2[f];
#pragma unroll
    for (int g = 0; g < 8; g++) {
        acc += g_ypart[(((f << 3) + g) << 15) + mb];
        acc += wLSI2[f * 24 + g]      * g_x1[(g << 15) + mb];
        acc += wLSI2[f * 24 + 8 + g]  * g_zs2a[(g << 15) + mb];
        acc += wLSI2[f * 24 + 16 + g] * g_zs2b[(g << 15) + mb];
    }
    g_y2[idx] = acc;
}

// ---------------------------------------------------------------------------
// 5) MLP layer 1: h[j][b] = sum_i W1[j][i] * yf[i][b]  (splitK, f32x2 packed)
// ---------------------------------------------------------------------------
__device__ __forceinline__ ULL ffma2(ULL a, ULL b, ULL c) {
    ULL d; asm("fma.rn.f32x2 %0, %1, %2, %3;" : "=l"(d) : "l"(a), "l"(b), "l"(c));
    return d;
}
__device__ __forceinline__ ULL packdup(float x) {
    ULL r; asm("mov.b64 %0, {%1, %1};" : "=l"(r) : "f"(x));
    return r;
}

__global__ __launch_bounds__(256) void k_mlp1(const float* __restrict__ W1) {
    __shared__ ULL sW[64 * 32];
    __shared__ __align__(16) float sX[32 * 64];
    int jt = blockIdx.x;      // 0..7
    int kt = blockIdx.y;      // 0..15
    int tid = threadIdx.x;
    int bp = tid & 31;
    int jg = tid >> 5;
    ULL acc[8];
#pragma unroll
    for (int jj = 0; jj < 8; jj++) acc[jj] = 0ull;

    for (int ic = 0; ic < 8; ic++) {
        int i0 = kt * 256 + ic * 32;
        {
            int ii = tid & 31; int jr0 = tid >> 5;
#pragma unroll
            for (int q = 0; q < 8; q++) {
                int jr = jr0 + (q << 3);
                sW[(jr << 5) + ii] = packdup(W1[(size_t)(jt * 64 + jr) * 4096 + i0 + ii]);
            }
            int b = tid & 63; int ii0 = tid >> 6;
#pragma unroll
            for (int q = 0; q < 8; q++) {
                int ii2 = ii0 + (q << 2);
                sX[(ii2 << 6) + b] = g_y2[(size_t)(i0 + ii2) * BATCH + b];
            }
        }
        __syncthreads();
#pragma unroll
        for (int ii = 0; ii < 32; ii++) {
            ULL xv = *reinterpret_cast<const ULL*>(&sX[(ii << 6) + (bp << 1)]);
#pragma unroll
            for (int jj = 0; jj < 8; jj++)
                acc[jj] = ffma2(sW[(((jg << 3) + jj) << 5) + ii], xv, acc[jj]);
        }
        __syncthreads();
    }
#pragma unroll
    for (int jj = 0; jj < 8; jj++) {
        int j = jt * 64 + (jg << 3) + jj;
        *reinterpret_cast<ULL*>(&g_hpart[((kt << 9) + j) * BATCH + (bp << 1)]) = acc[jj];
    }
}

__global__ void k_hreduce(const float* __restrict__ bW1) {
    int idx = blockIdx.x * blockDim.x + threadIdx.x;   // 512*64
    float s = bW1[idx >> 6];
#pragma unroll
    for (int kt = 0; kt < 16; kt++) s += g_hpart[(kt << 15) + idx];
    g_h1[idx] = s;
}

// ---------------------------------------------------------------------------
// 6) MLP layer 2: out[b][j2] = sum_j W2[j2][j] * h[j][b] + bW2[j2]
// ---------------------------------------------------------------------------
__global__ void k_mlp2(const float* __restrict__ W2, const float* __restrict__ bW2,
                       float* __restrict__ out) {
    int j2 = blockIdx.x; int b = threadIdx.x;
    float acc = 0.f;
#pragma unroll 8
    for (int j = 0; j < 512; j++)
        acc += W2[j2 * 512 + j] * g_h1[(j << 6) + b];
    out[b * 128 + j2] = acc + bW2[j2];
}

// ---------------------------------------------------------------------------
// launch
// ---------------------------------------------------------------------------
extern "C" void kernel_launch(void* const* d_in, const int* in_sizes, int n_in,
                              void* d_out, int out_size) {
    const float* x     = (const float*)d_in[0];
    const float* S     = (const float*)d_in[1];
    const float* wEV1  = (const float*)d_in[2];
    const float* wLSI1 = (const float*)d_in[3];
    const float* b1    = (const float*)d_in[4];
    const float* wEV2  = (const float*)d_in[5];
    const float* wLSI2 = (const float*)d_in[6];
    const float* b2    = (const float*)d_in[7];
    const float* W1    = (const float*)d_in[8];
    const float* bW1   = (const float*)d_in[9];
    const float* W2    = (const float*)d_in[10];
    const float* bW2   = (const float*)d_in[11];
    float* out = (float*)d_out;

    cudaFuncSetAttribute(k_evchain, cudaFuncAttributeMaxDynamicSharedMemorySize, 131072);

    k_build<<<64, 512>>>(S, x);                       // build + transpose
    k_spmv<<<128, 256>>>(0, 1);                       // S x
    k_spmv<<<128, 256>>>(1, 1);                       // S^2 x
    k_evchain<<<16, 512, 131072>>>(1, wEV1, wLSI1, b1);   // layer1 EV + combine1
    k_spmv<<<1024, 256>>>(2, 8);                      // S x1
    k_spmv<<<1024, 256>>>(3, 8);                      // S^2 x1
    k_evchain<<<128, 512, 131072>>>(2, wEV2, wLSI1, b1);  // layer2 EV -> ypart
    k_combine2<<<1024, 256>>>(wLSI2, b2);
    dim3 gm1(8, 16);
    k_mlp1<<<gm1, 256>>>(W1);
    k_hreduce<<<512, 64>>>(bW1);
    k_mlp2<<<128, 64>>>(W2, bW2, out);
}

// round 12
// speedup vs baseline: 1.8528x; 1.3607x over previous
#include <cuda_runtime.h>
#include <cstdint>

typedef unsigned long long ULL;

// ---------------------------------------------------------------------------
// Problem constants: B=64, N=512, E=1, M=256, F=[1,8,8], K=[3,3], MLP=[512,128]
// ---------------------------------------------------------------------------
#define NODES 512
#define BATCH 64
#define MAXNZ 64   // max nonzeros per row supported (actual ~16, max ~35)

// ------------------------- device scratch (no allocs) -----------------------
static __device__ int   g_sp_cnt[NODES];
static __device__ short g_sp_cols[NODES * MAXNZ];
static __device__ int   g_s_cnt[NODES];
static __device__ short g_s_cols[NODES * MAXNZ];
static __device__ float g_s_vals[NODES * MAXNZ];

static __device__ float g_x0[NODES * BATCH];           // x transposed [n][b]
static __device__ float g_zs1a[NODES * BATCH];         // S x
static __device__ float g_zs1b[NODES * BATCH];         // S^2 x
static __device__ float g_x1[8 * NODES * BATCH];       // layer1 output [g][n][b]
static __device__ float g_zs2a[8 * NODES * BATCH];     // S x1
static __device__ float g_zs2b[8 * NODES * BATCH];     // S^2 x1
static __device__ float g_ypart[64 * NODES * BATCH];   // layer2 EV partials [fg][n][b]
static __device__ float g_y2[8 * NODES * BATCH];       // layer2 output = yf [i][b]
static __device__ float g_hpart[16 * 512 * BATCH];     // MLP1 splitK partials
static __device__ float g_h1[512 * BATCH];             // MLP1 hidden [j][b]

// ---------------------------------------------------------------------------
// 1) Build sparse structures from S + transpose x, in one kernel.
// ---------------------------------------------------------------------------
__global__ __launch_bounds__(512) void k_build(const float* __restrict__ S,
                                               const float* __restrict__ x) {
    if (blockIdx.x >= 32) {
        __shared__ float tile[32][33];
        int tt = blockIdx.x - 32;
        int mt = tt >> 1, bt = tt & 1;
        int tx = threadIdx.x & 31, ty0 = threadIdx.x >> 5;
#pragma unroll
        for (int p = 0; p < 2; p++) {
            int ty = ty0 + (p << 4);
            tile[ty][tx] = x[(bt * 32 + ty) * NODES + mt * 32 + tx];
        }
        __syncthreads();
#pragma unroll
        for (int p = 0; p < 2; p++) {
            int ty = ty0 + (p << 4);
            g_x0[(mt * 32 + ty) * BATCH + bt * 32 + tx] = tile[tx][ty];
        }
        return;
    }
    int m = blockIdx.x * 16 + (threadIdx.x >> 5);
    int lane = threadIdx.x & 31;
    unsigned lt = (1u << lane) - 1u;
    float v[16];
#pragma unroll
    for (int r = 0; r < 16; r++) v[r] = __ldg(S + (m << 9) + (r << 5) + lane);
    int sc = 0, spc = 0;
#pragma unroll
    for (int r = 0; r < 16; r++) {
        int n = (r << 5) + lane;
        bool nz = (v[r] != 0.0f);
        unsigned bs = __ballot_sync(0xffffffffu, nz);
        if (nz) {
            int idx = sc + __popc(bs & lt);
            if (idx < MAXNZ) { g_s_cols[m * MAXNZ + idx] = (short)n; g_s_vals[m * MAXNZ + idx] = v[r]; }
        }
        sc += __popc(bs);
        bool insp = ((fabsf(v[r]) > 1e-9f) || (n == m)) && !((m >= 256) && (n >= 256));
        unsigned bp = __ballot_sync(0xffffffffu, insp);
        if (insp) {
            int idx = spc + __popc(bp & lt);
            if (idx < MAXNZ) g_sp_cols[m * MAXNZ + idx] = (short)n;
        }
        spc += __popc(bp);
    }
    if (lane == 0) {
        g_s_cnt[m]  = sc  < MAXNZ ? sc  : MAXNZ;
        g_sp_cnt[m] = spc < MAXNZ ? spc : MAXNZ;
    }
}

// ---------------------------------------------------------------------------
// 2) Sparse S matvec (LSI powers), shuffle-broadcast form.
// ---------------------------------------------------------------------------
__global__ __launch_bounds__(256) void k_spmv(int step, int nc) {
    const float* in; float* out;
    if (step == 0)      { in = g_x0;   out = g_zs1a; }
    else if (step == 1) { in = g_zs1a; out = g_zs1b; }
    else if (step == 2) { in = g_x1;   out = g_zs2a; }
    else                { in = g_zs2a; out = g_zs2b; }
    int gw = blockIdx.x * 8 + (threadIdx.x >> 5);
    int lane = threadIdx.x & 31;
    int c = gw >> 10;
    if (c >= nc) return;
    int m = (gw >> 1) & 511;
    int h = gw & 1;
    int cnt = g_s_cnt[m];
    float acc = 0.f;
    for (int jb = 0; jb < cnt; jb += 32) {
        int jn = cnt - jb; if (jn > 32) jn = 32;
        float sv = 0.f; int cv = 0;
        if (lane < jn) {
            cv = (int)g_s_cols[(m << 6) + jb + lane];
            sv = g_s_vals[(m << 6) + jb + lane];
        }
#pragma unroll 8
        for (int j = 0; j < jn; j++) {
            float wj = __shfl_sync(0xffffffffu, sv, j);
            int cj   = __shfl_sync(0xffffffffu, cv, j);
            acc += wj * __ldg(in + ((c << 9) + cj) * BATCH + (h << 5) + lane);
        }
    }
    out[((c << 9) + m) * BATCH + (h << 5) + lane] = acc;
}

// ---------------------------------------------------------------------------
// 3) EV chain kernel v2: half-warp per row, 2 batch elems per lane (float2).
//    Per j: 1 SHFL(w) + LDS.U16(byteoff) + LDS.64(z) + 2 FFMA.
//    z ping-pong (2x64KB); y = z1+z2+z3 recovered from the two buffers at k=2
//    (no register accumulator array). wEV read directly, depth-2 prefetch.
//    smem: z 131072 + scoff 32768 = 163840 dynamic.
// ---------------------------------------------------------------------------
__global__ __launch_bounds__(512, 1) void k_evchain(int layer,
                                                    const float* __restrict__ wEV,
                                                    const float* __restrict__ wLSI1,
                                                    const float* __restrict__ b1) {
    extern __shared__ char sraw[];
    float* zbuf0 = (float*)sraw;                               // [512][32]
    float* zbuf1 = (float*)(sraw + 65536);                     // [512][32]
    unsigned short* scoff = (unsigned short*)(sraw + 131072);  // [512][32] col<<7
    __shared__ int scnt[NODES];

    const int G = (layer == 1) ? 1 : 8;
    const float* xin = (layer == 1) ? g_x0 : g_x1;

    int h  = blockIdx.x & 1;
    int fg = blockIdx.x >> 1;
    int f  = (layer == 1) ? fg : (fg >> 3);
    int g  = (layer == 1) ? 0 : (fg & 7);
    int tid = threadIdx.x, w = tid >> 5, lane = tid & 31;
    int li = lane & 15, hb = lane & 16;    // half-lane index, half base

    scnt[tid] = g_sp_cnt[tid];
    for (int idx = tid; idx < NODES * 32; idx += 512)
        scoff[idx] = (unsigned short)((int)g_sp_cols[((idx >> 5) << 6) + (idx & 31)] << 7);
    for (int idx = tid; idx < NODES * 32; idx += 512)
        zbuf0[idx] = xin[((g << 9) + (idx >> 5)) * BATCH + (h << 5) + (idx & 31)];
    __syncthreads();

    const int pbase = f * 3 * G + g;

    auto pf = [&](int t, float& wlo, float& whi) {
        int kk = t >> 4, ii = t & 15;
        int myrow = (ii << 5) + hb + w;
        int cnt = scnt[myrow];
        const float* src = wEV + ((size_t)(pbase + kk * G) << 18) + (myrow << 9);
        int c0 = scoff[(myrow << 5) + li] >> 7;
        int c1 = scoff[(myrow << 5) + 16 + li] >> 7;
        wlo = (li < cnt)      ? __ldg(src + c0) : 0.f;
        whi = (li + 16 < cnt) ? __ldg(src + c1) : 0.f;
    };

    float wlo0, whi0, wlo1, whi1;
    pf(0, wlo0, whi0);
    pf(1, wlo1, whi1);

    const float* zr = zbuf0;
    float* zw = zbuf1;

    float wl0 = 0.f, wl1 = 0.f, wl2 = 0.f, bb = 0.f;
    if (layer == 1) { wl0 = wLSI1[f*3]; wl1 = wLSI1[f*3+1]; wl2 = wLSI1[f*3+2]; bb = b1[f]; }

    for (int t = 0; t < 48; t++) {
        float wlo2 = 0.f, whi2 = 0.f;
        if (t + 2 < 48) pf(t + 2, wlo2, whi2);

        int kk = t >> 4, ii = t & 15;
        int myrow = (ii << 5) + hb + w;
        int rA = (ii << 5) + w;
        int cA = scnt[rA], cB = scnt[rA + 16];
        int jmax = cA > cB ? cA : cB;
        int sbase = myrow << 5;
        const char* zb = (const char*)zr + (li << 3);
        float ax = 0.f, ay = 0.f;
        int j16 = jmax < 16 ? jmax : 16;
#pragma unroll 4
        for (int j = 0; j < j16; j++) {
            float wj = __shfl_sync(0xffffffffu, wlo0, hb + j);
            int off = scoff[sbase + j];
            float2 zv = *(const float2*)(zb + off);
            ax += wj * zv.x; ay += wj * zv.y;
        }
        if (jmax > 16) {
            int j32 = jmax < 32 ? jmax : 32;
#pragma unroll 4
            for (int j = 16; j < j32; j++) {
                float wj = __shfl_sync(0xffffffffu, whi0, hb + j - 16);
                int off = scoff[sbase + j];
                float2 zv = *(const float2*)(zb + off);
                ax += wj * zv.x; ay += wj * zv.y;
            }
        }
        if (jmax > 32) {   // rare tail (cnt up to 64 via global lists)
            int cmy = scnt[myrow];
            int rem = cmy - 32;
            int cv = 0; float wt = 0.f;
            if (rem > 0 && li < rem) {
                cv = (int)g_sp_cols[(myrow << 6) + 32 + li];
                wt = __ldg(wEV + ((size_t)(pbase + kk * G) << 18) + (myrow << 9) + cv);
            }
            int remMax = jmax - 32;
            for (int j = 0; j < remMax; j++) {
                float wj = __shfl_sync(0xffffffffu, wt, hb + j);
                int cj  = __shfl_sync(0xffffffffu, cv, hb + j);
                float2 zv = *(const float2*)((const char*)zr + (cj << 7) + (li << 3));
                ax += wj * zv.x; ay += wj * zv.y;
            }
        }

        if (kk < 2) {
            *(float2*)((char*)zw + (myrow << 7) + (li << 3)) = make_float2(ax, ay);
            if (ii == 15) {
                __syncthreads();
                const float* tz = zr; zr = zw; zw = (float*)tz;
            }
        } else {
            // zr = z2 (buf), zw = z1 (buf): y = z3(=acc) + z1 + z2
            float2 z1 = *(const float2*)((const char*)zw + (myrow << 7) + (li << 3));
            float2 z2 = *(const float2*)((const char*)zr + (myrow << 7) + (li << 3));
            float yx = ax + z1.x + z2.x;
            float yy = ay + z1.y + z2.y;
            int off = (myrow << 6) + (h << 5) + (li << 1);
            if (layer == 1) {
                float2 v0 = *(const float2*)&g_x0[off];
                float2 v1 = *(const float2*)&g_zs1a[off];
                float2 v2 = *(const float2*)&g_zs1b[off];
                yx += wl0 * v0.x + wl1 * v1.x + wl2 * v2.x + bb;
                yy += wl0 * v0.y + wl1 * v1.y + wl2 * v2.y + bb;
                *(float2*)&g_x1[(f << 15) + off] = make_float2(yx, yy);
            } else {
                *(float2*)&g_ypart[((size_t)fg << 15) + off] = make_float2(yx, yy);
            }
        }
        wlo0 = wlo1; whi0 = whi1;
        wlo1 = wlo2; whi1 = whi2;
    }
}

// ---------------------------------------------------------------------------
// 4) Combine layer2: y2 = sum_g ypart + sum_{k,g} wLSI2[f,k,g] * S^k x1 + b2[f]
// ---------------------------------------------------------------------------
__global__ void k_combine2(const float* __restrict__ wLSI2, const float* __restrict__ b2) {
    int idx = blockIdx.x * blockDim.x + threadIdx.x;   // 8*512*64
    int f = idx >> 15; int mb = idx & 32767;
    float acc = b2[f];
#pragma unroll
    for (int g = 0; g < 8; g++) {
        acc += g_ypart[(((f << 3) + g) << 15) + mb];
        acc += wLSI2[f * 24 + g]      * g_x1[(g << 15) + mb];
        acc += wLSI2[f * 24 + 8 + g]  * g_zs2a[(g << 15) + mb];
        acc += wLSI2[f * 24 + 16 + g] * g_zs2b[(g << 15) + mb];
    }
    g_y2[idx] = acc;
}

// ---------------------------------------------------------------------------
// 5) MLP layer 1: h[j][b] = sum_i W1[j][i] * yf[i][b]  (splitK, f32x2 packed)
// ---------------------------------------------------------------------------
__device__ __forceinline__ ULL ffma2(ULL a, ULL b, ULL c) {
    ULL d; asm("fma.rn.f32x2 %0, %1, %2, %3;" : "=l"(d) : "l"(a), "l"(b), "l"(c));
    return d;
}
__device__ __forceinline__ ULL packdup(float x) {
    ULL r; asm("mov.b64 %0, {%1, %1};" : "=l"(r) : "f"(x));
    return r;
}

__global__ __launch_bounds__(256) void k_mlp1(const float* __restrict__ W1) {
    __shared__ ULL sW[64 * 32];
    __shared__ __align__(16) float sX[32 * 64];
    int jt = blockIdx.x;      // 0..7
    int kt = blockIdx.y;      // 0..15
    int tid = threadIdx.x;
    int bp = tid & 31;
    int jg = tid >> 5;
    ULL acc[8];
#pragma unroll
    for (int jj = 0; jj < 8; jj++) acc[jj] = 0ull;

    for (int ic = 0; ic < 8; ic++) {
        int i0 = kt * 256 + ic * 32;
        {
            int ii = tid & 31; int jr0 = tid >> 5;
#pragma unroll
            for (int q = 0; q < 8; q++) {
                int jr = jr0 + (q << 3);
                sW[(jr << 5) + ii] = packdup(W1[(size_t)(jt * 64 + jr) * 4096 + i0 + ii]);
            }
            int b = tid & 63; int ii0 = tid >> 6;
#pragma unroll
            for (int q = 0; q < 8; q++) {
                int ii2 = ii0 + (q << 2);
                sX[(ii2 << 6) + b] = g_y2[(size_t)(i0 + ii2) * BATCH + b];
            }
        }
        __syncthreads();
#pragma unroll
        for (int ii = 0; ii < 32; ii++) {
            ULL xv = *reinterpret_cast<const ULL*>(&sX[(ii << 6) + (bp << 1)]);
#pragma unroll
            for (int jj = 0; jj < 8; jj++)
                acc[jj] = ffma2(sW[(((jg << 3) + jj) << 5) + ii], xv, acc[jj]);
        }
        __syncthreads();
    }
#pragma unroll
    for (int jj = 0; jj < 8; jj++) {
        int j = jt * 64 + (jg << 3) + jj;
        *reinterpret_cast<ULL*>(&g_hpart[((kt << 9) + j) * BATCH + (bp << 1)]) = acc[jj];
    }
}

__global__ void k_hreduce(const float* __restrict__ bW1) {
    int idx = blockIdx.x * blockDim.x + threadIdx.x;   // 512*64
    float s = bW1[idx >> 6];
#pragma unroll
    for (int kt = 0; kt < 16; kt++) s += g_hpart[(kt << 15) + idx];
    g_h1[idx] = s;
}

// ---------------------------------------------------------------------------
// 6) MLP layer 2: out[b][j2] = sum_j W2[j2][j] * h[j][b] + bW2[j2]
// ---------------------------------------------------------------------------
__global__ void k_mlp2(const float* __restrict__ W2, const float* __restrict__ bW2,
                       float* __restrict__ out) {
    int j2 = blockIdx.x; int b = threadIdx.x;
    float acc = 0.f;
#pragma unroll 8
    for (int j = 0; j < 512; j++)
        acc += W2[j2 * 512 + j] * g_h1[(j << 6) + b];
    out[b * 128 + j2] = acc + bW2[j2];
}

// ---------------------------------------------------------------------------
// launch
// ---------------------------------------------------------------------------
extern "C" void kernel_launch(void* const* d_in, const int* in_sizes, int n_in,
                              void* d_out, int out_size) {
    const float* x     = (const float*)d_in[0];
    const float* S     = (const float*)d_in[1];
    const float* wEV1  = (const float*)d_in[2];
    const float* wLSI1 = (const float*)d_in[3];
    const float* b1    = (const float*)d_in[4];
    const float* wEV2  = (const float*)d_in[5];
    const float* wLSI2 = (const float*)d_in[6];
    const float* b2    = (const float*)d_in[7];
    const float* W1    = (const float*)d_in[8];
    const float* bW1   = (const float*)d_in[9];
    const float* W2    = (const float*)d_in[10];
    const float* bW2   = (const float*)d_in[11];
    float* out = (float*)d_out;

    cudaFuncSetAttribute(k_evchain, cudaFuncAttributeMaxDynamicSharedMemorySize, 163840);

    k_build<<<64, 512>>>(S, x);                       // build + transpose
    k_spmv<<<128, 256>>>(0, 1);                       // S x
    k_spmv<<<128, 256>>>(1, 1);                       // S^2 x
    k_evchain<<<16, 512, 163840>>>(1, wEV1, wLSI1, b1);   // layer1 EV + combine1
    k_spmv<<<1024, 256>>>(2, 8);                      // S x1
    k_spmv<<<1024, 256>>>(3, 8);                      // S^2 x1
    k_evchain<<<128, 512, 163840>>>(2, wEV2, wLSI1, b1);  // layer2 EV -> ypart
    k_combine2<<<1024, 256>>>(wLSI2, b2);
    dim3 gm1(8, 16);
    k_mlp1<<<gm1, 256>>>(W1);
    k_hreduce<<<512, 64>>>(bW1);
    k_mlp2<<<128, 64>>>(W2, bW2, out);
}

// round 15
// speedup vs baseline: 2.2771x; 1.2290x over previous
#include <cuda_runtime.h>
#include <cstdint>

typedef unsigned long long ULL;

// ---------------------------------------------------------------------------
// Problem constants: B=64, N=512, E=1, M=256, F=[1,8,8], K=[3,3], MLP=[512,128]
// ---------------------------------------------------------------------------
#define NODES 512
#define BATCH 64
#define MAXNZ 64   // max nonzeros per row supported (actual ~16, max ~35)

// ------------------------- device scratch (no allocs) -----------------------
static __device__ int   g_sp_cnt[NODES];
static __device__ short g_sp_cols[NODES * MAXNZ];
static __device__ int   g_s_cnt[NODES];
static __device__ short g_s_cols[NODES * MAXNZ];
static __device__ float g_s_vals[NODES * MAXNZ];

static __device__ float g_x0[NODES * BATCH];           // x transposed [n][b]
static __device__ float g_zs1a[NODES * BATCH];         // S x
static __device__ float g_zs1b[NODES * BATCH];         // S^2 x
static __device__ float g_ezA[8 * NODES * BATCH];      // layer1 z1 [f][n][b]
static __device__ float g_ezB[8 * NODES * BATCH];      // layer1 z2 [f][n][b]
static __device__ float g_x1[8 * NODES * BATCH];       // layer1 output [g][n][b]
static __device__ float g_zs2a[8 * NODES * BATCH];     // S x1
static __device__ float g_zs2b[8 * NODES * BATCH];     // S^2 x1
static __device__ float g_ypart[64 * NODES * BATCH];   // layer2 EV partials [fg][n][b]
static __device__ float g_y2[8 * NODES * BATCH];       // layer2 output = yf [i][b]
static __device__ float g_hpart[16 * 512 * BATCH];     // MLP1 splitK partials
static __device__ float g_h1[512 * BATCH];             // MLP1 hidden [j][b]

// ---------------------------------------------------------------------------
// 1) Build sparse structures from S + transpose x, in one kernel.
// ---------------------------------------------------------------------------
__global__ __launch_bounds__(512) void k_build(const float* __restrict__ S,
                                               const float* __restrict__ x) {
    if (blockIdx.x >= 32) {
        __shared__ float tile[32][33];
        int tt = blockIdx.x - 32;
        int mt = tt >> 1, bt = tt & 1;
        int tx = threadIdx.x & 31, ty0 = threadIdx.x >> 5;
#pragma unroll
        for (int p = 0; p < 2; p++) {
            int ty = ty0 + (p << 4);
            tile[ty][tx] = x[(bt * 32 + ty) * NODES + mt * 32 + tx];
        }
        __syncthreads();
#pragma unroll
        for (int p = 0; p < 2; p++) {
            int ty = ty0 + (p << 4);
            g_x0[(mt * 32 + ty) * BATCH + bt * 32 + tx] = tile[tx][ty];
        }
        return;
    }
    int m = blockIdx.x * 16 + (threadIdx.x >> 5);
    int lane = threadIdx.x & 31;
    unsigned lt = (1u << lane) - 1u;
    float v[16];
#pragma unroll
    for (int r = 0; r < 16; r++) v[r] = __ldg(S + (m << 9) + (r << 5) + lane);
    int sc = 0, spc = 0;
#pragma unroll
    for (int r = 0; r < 16; r++) {
        int n = (r << 5) + lane;
        bool nz = (v[r] != 0.0f);
        unsigned bs = __ballot_sync(0xffffffffu, nz);
        if (nz) {
            int idx = sc + __popc(bs & lt);
            if (idx < MAXNZ) { g_s_cols[m * MAXNZ + idx] = (short)n; g_s_vals[m * MAXNZ + idx] = v[r]; }
        }
        sc += __popc(bs);
        bool insp = ((fabsf(v[r]) > 1e-9f) || (n == m)) && !((m >= 256) && (n >= 256));
        unsigned bp = __ballot_sync(0xffffffffu, insp);
        if (insp) {
            int idx = spc + __popc(bp & lt);
            if (idx < MAXNZ) g_sp_cols[m * MAXNZ + idx] = (short)n;
        }
        spc += __popc(bp);
    }
    if (lane == 0) {
        g_s_cnt[m]  = sc  < MAXNZ ? sc  : MAXNZ;
        g_sp_cnt[m] = spc < MAXNZ ? spc : MAXNZ;
    }
}

// ---------------------------------------------------------------------------
// 2) Layer-1 EV as 3 global-z steps (full-chip parallel, z is L2-resident).
//    Warp = (fp, row): fp 0..7 = EV chains, fp 8 = LSI S-power matvec.
//    Lane l handles batch pair (2l, 2l+1) as float2.
//    k=0: z1 = Phi0 x       ; zs1a = S x
//    k=1: z2 = Phi1 z1      ; zs1b = S zs1a
//    k=2: z3 = Phi2 z2, then x1 = z1+z2+z3 + sum_k wLSI1[f,k] S^k x + b1[f]
// ---------------------------------------------------------------------------
__global__ __launch_bounds__(256) void k_ev1(int k, const float* __restrict__ wEV1,
                                             const float* __restrict__ wLSI1,
                                             const float* __restrict__ b1) {
    int gw = blockIdx.x * 8 + (threadIdx.x >> 5);
    int lane = threadIdx.x & 31;
    int fp = gw >> 9;          // 0..8
    int m  = gw & 511;

    const float* zin; float* zout;
    int cnt;
    if (fp == 8) {
        if (k == 2) return;
        cnt  = g_s_cnt[m];
        zin  = (k == 0) ? g_x0 : g_zs1a;
        zout = (k == 0) ? g_zs1a : g_zs1b;
    } else {
        cnt  = g_sp_cnt[m];
        zin  = (k == 0) ? g_x0 : ((k == 1) ? g_ezA + (fp << 15) : g_ezB + (fp << 15));
        zout = (k == 0) ? g_ezA + (fp << 15) : ((k == 1) ? g_ezB + (fp << 15) : 0);
    }
    const float* wpl = (fp < 8) ? (wEV1 + ((size_t)(fp * 3 + k) << 18)) : 0;

    float ax = 0.f, ay = 0.f;
    for (int jb = 0; jb < cnt; jb += 32) {
        int jn = cnt - jb; if (jn > 32) jn = 32;
        int cv = 0; float wv = 0.f;
        if (lane < jn) {
            if (fp == 8) {
                cv = (int)g_s_cols[(m << 6) + jb + lane];
                wv = g_s_vals[(m << 6) + jb + lane];
            } else {
                cv = (int)g_sp_cols[(m << 6) + jb + lane];
                wv = __ldg(wpl + (m << 9) + cv);
            }
        }
#pragma unroll 8
        for (int j = 0; j < jn; j++) {
            float wj = __shfl_sync(0xffffffffu, wv, j);
            int   cj = __shfl_sync(0xffffffffu, cv, j);
            float2 zv = *(const float2*)&zin[(cj << 6) + (lane << 1)];
            ax += wj * zv.x; ay += wj * zv.y;
        }
    }

    int off = (m << 6) + (lane << 1);
    if (fp == 8 || k < 2) {
        *(float2*)&zout[off] = make_float2(ax, ay);
    } else {
        // fused combine1
        float2 z1 = *(const float2*)&g_ezA[(fp << 15) + off];
        float2 z2 = *(const float2*)&g_ezB[(fp << 15) + off];
        float2 v0 = *(const float2*)&g_x0[off];
        float2 v1 = *(const float2*)&g_zs1a[off];
        float2 v2 = *(const float2*)&g_zs1b[off];
        float wl0 = wLSI1[fp * 3], wl1 = wLSI1[fp * 3 + 1], wl2 = wLSI1[fp * 3 + 2];
        float bb = b1[fp];
        float yx = ax + z1.x + z2.x + wl0 * v0.x + wl1 * v1.x + wl2 * v2.x + bb;
        float yy = ay + z1.y + z2.y + wl0 * v0.y + wl1 * v1.y + wl2 * v2.y + bb;
        *(float2*)&g_x1[(fp << 15) + off] = make_float2(yx, yy);
    }
}

// ---------------------------------------------------------------------------
// 3) Sparse S matvec (LSI powers for layer 2), shuffle-broadcast form.
// ---------------------------------------------------------------------------
__global__ __launch_bounds__(256) void k_spmv(int step, int nc) {
    const float* in; float* out;
    if (step == 2) { in = g_x1;   out = g_zs2a; }
    else           { in = g_zs2a; out = g_zs2b; }
    int gw = blockIdx.x * 8 + (threadIdx.x >> 5);
    int lane = threadIdx.x & 31;
    int c = gw >> 10;
    if (c >= nc) return;
    int m = (gw >> 1) & 511;
    int h = gw & 1;
    int cnt = g_s_cnt[m];
    float acc = 0.f;
    for (int jb = 0; jb < cnt; jb += 32) {
        int jn = cnt - jb; if (jn > 32) jn = 32;
        float sv = 0.f; int cv = 0;
        if (lane < jn) {
            cv = (int)g_s_cols[(m << 6) + jb + lane];
            sv = g_s_vals[(m << 6) + jb + lane];
        }
#pragma unroll 8
        for (int j = 0; j < jn; j++) {
            float wj = __shfl_sync(0xffffffffu, sv, j);
            int cj   = __shfl_sync(0xffffffffu, cv, j);
            acc += wj * __ldg(in + ((c << 9) + cj) * BATCH + (h << 5) + lane);
        }
    }
    out[((c << 9) + m) * BATCH + (h << 5) + lane] = acc;
}

// ---------------------------------------------------------------------------
// 4) Layer-2 EV chain kernel v3: half-warp per row, float2 per lane.
//    (w, z-byte-offset) pairs staged in per-warp smem 2 iterations ahead;
//    inner j: LDS.64 pair + IADD + LDS.64 z + 2 FFMA (no SHFL chains).
//    z ping-pong (2x64KB); y = z1+z2+z3 from the two buffers at k=2.
//    dyn smem: z 131072 + scoff 32768 + wpair 24576 = 188416.
// ---------------------------------------------------------------------------
__global__ __launch_bounds__(512, 1) void k_evchain(const float* __restrict__ wEV) {
    extern __shared__ char sraw[];
    float* zbuf0 = (float*)sraw;                               // [512][32]
    float* zbuf1 = (float*)(sraw + 65536);                     // [512][32]
    unsigned short* scoff = (unsigned short*)(sraw + 131072);  // [512][32] col<<7
    float2* wpair = (float2*)(sraw + 163840);                  // [16 warps][3 slots][64]
    __shared__ int scnt[NODES];

    const int G = 8;
    int h  = blockIdx.x & 1;
    int fg = blockIdx.x >> 1;
    int f  = fg >> 3;
    int g  = fg & 7;
    int tid = threadIdx.x, w = tid >> 5, lane = tid & 31;
    int li = lane & 15, hb = lane & 16;    // half-lane index, half base (0/16)

    scnt[tid] = g_sp_cnt[tid];
    for (int idx = tid; idx < NODES * 32; idx += 512)
        scoff[idx] = (unsigned short)((int)g_sp_cols[((idx >> 5) << 6) + (idx & 31)] << 7);
    for (int idx = tid; idx < NODES * 32; idx += 512)
        zbuf0[idx] = g_x1[((g << 9) + (idx >> 5)) * BATCH + (h << 5) + (idx & 31)];
    __syncthreads();

    const int pbase = f * 3 * G + g;
    const char* wb = (const char*)wEV;

    // stage (w, off) pairs for row-iteration t into slot
    auto pf = [&](int t, int slot) {
        int kk = t >> 4, ii = t & 15;
        int myrow = (ii << 5) + hb + w;
        int cnt = scnt[myrow];
        unsigned wo = ((unsigned)(pbase + kk * G) << 20) + ((unsigned)myrow << 11);
        unsigned short o0 = scoff[(myrow << 5) + li];
        unsigned short o1 = scoff[(myrow << 5) + 16 + li];
        float wlo = (li < cnt)      ? __ldg((const float*)(wb + wo + ((unsigned)o0 >> 5))) : 0.f;
        float whi = (li + 16 < cnt) ? __ldg((const float*)(wb + wo + ((unsigned)o1 >> 5))) : 0.f;
        float2* wp = wpair + ((w * 3 + slot) << 6) + (hb << 1);
        wp[li]      = make_float2(wlo, __int_as_float((int)o0));
        wp[16 + li] = make_float2(whi, __int_as_float((int)o1));
    };

    pf(0, 0);
    pf(1, 1);
    __syncwarp();

    const float* zr = zbuf0;
    float* zw = zbuf1;
    int scur = 0, spre = 2;

    for (int t = 0; t < 48; t++) {
        if (t + 2 < 48) pf(t + 2, spre);
        __syncwarp();

        int kk = t >> 4, ii = t & 15;
        int myrow = (ii << 5) + hb + w;
        int rA = (ii << 5) + w;
        int cA = scnt[rA], cB = scnt[rA + 16];
        int jmax = cA > cB ? cA : cB;
        int jm = jmax < 32 ? jmax : 32;

        const float2* wp = wpair + ((w * 3 + scur) << 6) + (hb << 1);
        const char* zb = (const char*)zr + (li << 3);
        float ax = 0.f, ay = 0.f;
#pragma unroll 4
        for (int j = 0; j < jm; j++) {
            float2 p = wp[j];
            float2 zv = *(const float2*)(zb + __float_as_int(p.y));
            ax += p.x * zv.x; ay += p.x * zv.y;
        }
        if (jmax > 32) {   // rare tail (cnt up to 64 via global lists)
            int cmy = scnt[myrow];
            int rem = cmy - 32;
            int cv = 0; float wt = 0.f;
            if (rem > 0 && li < rem) {
                cv = (int)g_sp_cols[(myrow << 6) + 32 + li];
                wt = __ldg((const float*)(wb + (((unsigned)(pbase + kk * G) << 20)
                                               + ((unsigned)myrow << 11) + ((unsigned)cv << 2))));
            }
            int remMax = jmax - 32;
            for (int j = 0; j < remMax; j++) {
                float wj = __shfl_sync(0xffffffffu, wt, hb + j);
                int cj  = __shfl_sync(0xffffffffu, cv, hb + j);
                float2 zv = *(const float2*)((const char*)zr + (cj << 7) + (li << 3));
                ax += wj * zv.x; ay += wj * zv.y;
            }
        }

        if (kk < 2) {
            *(float2*)((char*)zw + (myrow << 7) + (li << 3)) = make_float2(ax, ay);
            if (ii == 15) {
                __syncthreads();
                const float* tz = zr; zr = zw; zw = (float*)tz;
            }
        } else {
            // zr = z2 (buf), zw = z1 (buf): y = z3(=acc) + z1 + z2
            float2 z1 = *(const float2*)((const char*)zw + (myrow << 7) + (li << 3));
            float2 z2 = *(const float2*)((const char*)zr + (myrow << 7) + (li << 3));
            int off = (myrow << 6) + (h << 5) + (li << 1);
            *(float2*)&g_ypart[((size_t)fg << 15) + off] =
                make_float2(ax + z1.x + z2.x, ay + z1.y + z2.y);
        }
        scur++; if (scur == 3) scur = 0;
        spre++; if (spre == 3) spre = 0;
    }
}

// ---------------------------------------------------------------------------
// 5) Combine layer2: y2 = sum_g ypart + sum_{k,g} wLSI2[f,k,g] * S^k x1 + b2[f]
// ---------------------------------------------------------------------------
__global__ void k_combine2(const float* __restrict__ wLSI2, const float* __restrict__ b2) {
    int idx = blockIdx.x * blockDim.x + threadIdx.x;   // 8*512*64
    int f = idx >> 15; int mb = idx & 32767;
    float acc = b2[f];
#pragma unroll
    for (int g = 0; g < 8; g++) {
        acc += g_ypart[(((f << 3) + g) << 15) + mb];
        acc += wLSI2[f * 24 + g]      * g_x1[(g << 15) + mb];
        acc += wLSI2[f * 24 + 8 + g]  * g_zs2a[(g << 15) + mb];
        acc += wLSI2[f * 24 + 16 + g] * g_zs2b[(g << 15) + mb];
    }
    g_y2[idx] = acc;
}

// ---------------------------------------------------------------------------
// 6) MLP layer 1: h[j][b] = sum_i W1[j][i] * yf[i][b]  (splitK, f32x2 packed)
// ---------------------------------------------------------------------------
__device__ __forceinline__ ULL ffma2(ULL a, ULL b, ULL c) {
    ULL d; asm("fma.rn.f32x2 %0, %1, %2, %3;" : "=l"(d) : "l"(a), "l"(b), "l"(c));
    return d;
}
__device__ __forceinline__ ULL packdup(float x) {
    ULL r; asm("mov.b64 %0, {%1, %1};" : "=l"(r) : "f"(x));
    return r;
}

__global__ __launch_bounds__(256) void k_mlp1(const float* __restrict__ W1) {
    __shared__ ULL sW[64 * 32];
    __shared__ __align__(16) float sX[32 * 64];
    int jt = blockIdx.x;      // 0..7
    int kt = blockIdx.y;      // 0..15
    int tid = threadIdx.x;
    int bp = tid & 31;
    int jg = tid >> 5;
    ULL acc[8];
#pragma unroll
    for (int jj = 0; jj < 8; jj++) acc[jj] = 0ull;

    for (int ic = 0; ic < 8; ic++) {
        int i0 = kt * 256 + ic * 32;
        {
            int ii = tid & 31; int jr0 = tid >> 5;
#pragma unroll
            for (int q = 0; q < 8; q++) {
                int jr = jr0 + (q << 3);
                sW[(jr << 5) + ii] = packdup(W1[(size_t)(jt * 64 + jr) * 4096 + i0 + ii]);
            }
            int b = tid & 63; int ii0 = tid >> 6;
#pragma unroll
            for (int q = 0; q < 8; q++) {
                int ii2 = ii0 + (q << 2);
                sX[(ii2 << 6) + b] = g_y2[(size_t)(i0 + ii2) * BATCH + b];
            }
        }
        __syncthreads();
#pragma unroll
        for (int ii = 0; ii < 32; ii++) {
            ULL xv = *reinterpret_cast<const ULL*>(&sX[(ii << 6) + (bp << 1)]);
#pragma unroll
            for (int jj = 0; jj < 8; jj++)
                acc[jj] = ffma2(sW[(((jg << 3) + jj) << 5) + ii], xv, acc[jj]);
        }
        __syncthreads();
    }
#pragma unroll
    for (int jj = 0; jj < 8; jj++) {
        int j = jt * 64 + (jg << 3) + jj;
        *reinterpret_cast<ULL*>(&g_hpart[((kt << 9) + j) * BATCH + (bp << 1)]) = acc[jj];
    }
}

__global__ void k_hreduce(const float* __restrict__ bW1) {
    int idx = blockIdx.x * blockDim.x + threadIdx.x;   // 512*64
    float s = bW1[idx >> 6];
#pragma unroll
    for (int kt = 0; kt < 16; kt++) s += g_hpart[(kt << 15) + idx];
    g_h1[idx] = s;
}

// ---------------------------------------------------------------------------
// 7) MLP layer 2: out[b][j2] = sum_j W2[j2][j] * h[j][b] + bW2[j2]
// ---------------------------------------------------------------------------
__global__ void k_mlp2(const float* __restrict__ W2, const float* __restrict__ bW2,
                       float* __restrict__ out) {
    int j2 = blockIdx.x; int b = threadIdx.x;
    float acc = 0.f;
#pragma unroll 8
    for (int j = 0; j < 512; j++)
        acc += W2[j2 * 512 + j] * g_h1[(j << 6) + b];
    out[b * 128 + j2] = acc + bW2[j2];
}

// ---------------------------------------------------------------------------
// launch
// ---------------------------------------------------------------------------
extern "C" void kernel_launch(void* const* d_in, const int* in_sizes, int n_in,
                              void* d_out, int out_size) {
    const float* x     = (const float*)d_in[0];
    const float* S     = (const float*)d_in[1];
    const float* wEV1  = (const float*)d_in[2];
    const float* wLSI1 = (const float*)d_in[3];
    const float* b1    = (const float*)d_in[4];
    const float* wEV2  = (const float*)d_in[5];
    const float* wLSI2 = (const float*)d_in[6];
    const float* b2    = (const float*)d_in[7];
    const float* W1    = (const float*)d_in[8];
    const float* bW1   = (const float*)d_in[9];
    const float* W2    = (const float*)d_in[10];
    const float* bW2   = (const float*)d_in[11];
    float* out = (float*)d_out;

    cudaFuncSetAttribute(k_evchain, cudaFuncAttributeMaxDynamicSharedMemorySize, 188416);

    k_build<<<64, 512>>>(S, x);                       // build + transpose
    k_ev1<<<576, 256>>>(0, wEV1, wLSI1, b1);          // z1 = Phi0 x ; zs1a = S x
    k_ev1<<<576, 256>>>(1, wEV1, wLSI1, b1);          // z2 = Phi1 z1 ; zs1b = S^2 x
    k_ev1<<<576, 256>>>(2, wEV1, wLSI1, b1);          // z3 + combine1 -> x1
    k_spmv<<<1024, 256>>>(2, 8);                      // S x1
    k_spmv<<<1024, 256>>>(3, 8);                      // S^2 x1
    k_evchain<<<128, 512, 188416>>>(wEV2);            // layer2 EV -> ypart
    k_combine2<<<1024, 256>>>(wLSI2, b2);
    dim3 gm1(8, 16);
    k_mlp1<<<gm1, 256>>>(W1);
    k_hreduce<<<512, 64>>>(bW1);
    k_mlp2<<<128, 64>>>(W2, bW2, out);
}